// round 9
// baseline (speedup 1.0000x reference)
#include <cuda_runtime.h>
#include <cuda_fp16.h>
#include <cstdint>

#define T_DIM   8192
#define IN_DIM  4096
#define OUT_DIM 4096
#define R_DIM   256
#define SCALE_F 4.0f
#define NSM     148
#define NTILES  1024   /* 16 (o/256) x 64 (t/128) */

// Tiled + SW128-pre-swizzled fp16 operand buffers (16KB tiles: 128 rows x 64 cols)
__device__ __align__(128) __half g_xhi[(size_t)T_DIM  * IN_DIM];
__device__ __align__(128) __half g_whi[(size_t)OUT_DIM * IN_DIM];
__device__ __align__(128) __half g_bh [(size_t)OUT_DIM * R_DIM];
__device__ __align__(128) __half g_ahT[(size_t)IN_DIM  * R_DIM];

// ---------------------------------------------------------------------------
// helpers
// ---------------------------------------------------------------------------
static __device__ __forceinline__ uint32_t sw128(uint32_t b) {
    return b ^ ((b >> 3) & 0x70);
}
static __device__ __forceinline__ uint32_t smem_u32(const void* p) {
    uint32_t a;
    asm("{ .reg .u64 t; cvta.to.shared.u64 t, %1; cvt.u32.u64 %0, t; }"
        : "=r"(a) : "l"(p));
    return a;
}
static __device__ __forceinline__ uint32_t h2u(__half a, __half b) {
    __half2 h = __halves2half2(a, b);
    return *(uint32_t*)&h;
}

#define MBARRIER_INIT(m, c) \
    asm volatile("mbarrier.init.shared.b64 [%0], %1;" :: "r"(m), "r"((uint32_t)(c)) : "memory")
#define MBARRIER_EXPECT_TX(m, b) \
    asm volatile("mbarrier.arrive.expect_tx.shared.b64 _, [%0], %1;" :: "r"(m), "r"((uint32_t)(b)) : "memory")
#define MBARRIER_ARRIVE(m) \
    asm volatile("mbarrier.arrive.shared.b64 _, [%0];" :: "r"(m) : "memory")

#define WAIT_PARITY(m, p) do {                                                    \
    uint32_t _m = (m), _p = (uint32_t)(p), _d;                                    \
    asm volatile("{\n\t.reg .pred P;\n\t"                                         \
        "mbarrier.try_wait.parity.acquire.cta.shared::cta.b64 P, [%1], %2;\n\t"   \
        "selp.b32 %0, 1, 0, P;\n\t}" : "=r"(_d) : "r"(_m), "r"(_p) : "memory");   \
    while (!_d) {                                                                 \
        asm volatile("{\n\t.reg .pred P;\n\t"                                     \
            "mbarrier.try_wait.parity.acquire.cta.shared::cta.b64 P, [%1], %2, 0x989680;\n\t" \
            "selp.b32 %0, 1, 0, P;\n\t}" : "=r"(_d) : "r"(_m), "r"(_p) : "memory"); \
    } } while (0)

static __device__ __forceinline__ void bulk_g2s(uint32_t dst, const void* src,
                                                uint32_t bytes, uint32_t mbar) {
    unsigned long long g = (unsigned long long)__cvta_generic_to_global(src);
    asm volatile("cp.async.bulk.shared::cta.global.mbarrier::complete_tx::bytes [%0], [%1], %2, [%3];"
                 :: "r"(dst), "l"(g), "r"(bytes), "r"(mbar) : "memory");
}

#define LDSM_X4(r, addr) \
    asm volatile("ldmatrix.sync.aligned.m8n8.x4.shared.b16 {%0,%1,%2,%3}, [%4];" \
                 : "=r"((r)[0]), "=r"((r)[1]), "=r"((r)[2]), "=r"((r)[3]) : "r"(addr))

#define MMA16816(c, a, b0, b1) \
    asm volatile("mma.sync.aligned.m16n8k16.row.col.f32.f16.f16.f32 " \
                 "{%0,%1,%2,%3}, {%4,%5,%6,%7}, {%8,%9}, {%0,%1,%2,%3};" \
                 : "+f"((c)[0]), "+f"((c)[1]), "+f"((c)[2]), "+f"((c)[3]) \
                 : "r"((a)[0]), "r"((a)[1]), "r"((a)[2]), "r"((a)[3]), \
                   "r"(b0), "r"(b1))

// ---------------------------------------------------------------------------
// Kernel 1: tiny conv — Bh and AhT fp16 tiles (must precede vera_mid)
// ---------------------------------------------------------------------------
__global__ __launch_bounds__(256) void vera_conv(
    const float* __restrict__ vB, const float* __restrict__ vb,
    const float* __restrict__ vA, const float* __restrict__ vd)
{
    const uint32_t blk = blockIdx.x;
    if (blk < 512) {
        // Bh = fp16( (SCALE/64) * b[o] * vB[o][r] )
        const uint32_t c    = blk * 256 + threadIdx.x;
        const uint32_t o    = c >> 5;
        const uint32_t r8   = c & 31;
        const uint32_t rblk = r8 >> 3;
        const uint32_t cu   = (r8 & 7) * 8;

        const float s = __ldg(&vb[o]) * (SCALE_F / 64.0f);
        const float* src = vB + (size_t)o * R_DIM + rblk * 64 + cu;
        float4 a = *(const float4*)src;
        float4 b = *(const float4*)(src + 4);
        __half h[8] = {__float2half_rn(a.x * s), __float2half_rn(a.y * s),
                       __float2half_rn(a.z * s), __float2half_rn(a.w * s),
                       __float2half_rn(b.x * s), __float2half_rn(b.y * s),
                       __float2half_rn(b.z * s), __float2half_rn(b.w * s)};
        uint4 v = make_uint4(h2u(h[0], h[1]), h2u(h[2], h[3]),
                             h2u(h[4], h[5]), h2u(h[6], h[7]));
        const size_t tile = ((size_t)(o >> 7) * 4 + rblk) * 16384;
        const uint32_t off = sw128((o & 127) * 128 + cu * 2);
        *(uint4*)((char*)g_bh + tile + off) = v;
    } else {
        // AhT[i][r] = fp16( 64 * d[r] * vA[r][i] )  (transpose)
        const uint32_t c  = (blk - 512) * 256 + threadIdx.x;
        const uint32_t r  = c >> 10;
        const uint32_t i4 = (c & 1023) * 4;

        const float s = __ldg(&vd[r]) * 64.0f;
        float4 v = *(const float4*)&vA[(size_t)r * IN_DIM + i4];
        const float vv[4] = {v.x, v.y, v.z, v.w};
#pragma unroll
        for (int j = 0; j < 4; j++) {
            const uint32_t i = i4 + j;
            const size_t tile = ((size_t)(i >> 7) * 4 + (r >> 6)) * 16384;
            const uint32_t off = sw128((i & 127) * 128 + (r & 63) * 2);
            *(__half*)((char*)g_ahT + tile + off) = __float2half_rn(vv[j] * s);
        }
    }
}

// ---------------------------------------------------------------------------
// Kernel 2: FUSED middle stage — weff HMMA (blocks [0,1024)) runs
// concurrently with x fp16 conversion (blocks [1024,17408)).
//   weff: M=128(o) x N=128(i), K=256, 3-stage, 2 CTA/SM.
//   xconv: DRAM-bound, no smem, backfills SMs as weff drains.
// ---------------------------------------------------------------------------
#define WSTG_B  32768
#define WSMEM   (1024 + 3 * WSTG_B)

__global__ __launch_bounds__(256, 2) void vera_mid(
    const float* __restrict__ x, const float* __restrict__ W)
{
    const uint32_t blk = blockIdx.x;

    if (blk >= 1024) {
        // ---------------- x convert path ----------------
        const uint32_t c    = (blk - 1024) * 256 + threadIdx.x;
        const uint32_t k8   = c & 511;
        const uint32_t t    = c >> 9;
        const uint32_t kblk = k8 >> 3;
        const uint32_t cu   = (k8 & 7) * 8;
        const uint32_t row  = t & 127;
        const uint32_t mblk = t >> 7;

        const float* src = x + (size_t)t * IN_DIM + kblk * 64 + cu;
        float4 a = *(const float4*)src;
        float4 b = *(const float4*)(src + 4);
        __half2 p0 = __floats2half2_rn(a.x, a.y);
        __half2 p1 = __floats2half2_rn(a.z, a.w);
        __half2 p2 = __floats2half2_rn(b.x, b.y);
        __half2 p3 = __floats2half2_rn(b.z, b.w);
        uint4 v = make_uint4(*(uint32_t*)&p0, *(uint32_t*)&p1,
                             *(uint32_t*)&p2, *(uint32_t*)&p3);
        const uint32_t off = sw128(row * 128 + cu * 2);
        *(uint4*)((char*)g_xhi + ((size_t)mblk * 64 + kblk) * 16384 + off) = v;
        return;
    }

    // ---------------- weff HMMA path ----------------
    extern __shared__ char smem[];
    const uint32_t sb = smem_u32(smem);
    const int tid  = threadIdx.x;
    const int lane = tid & 31;
    const int wid  = tid >> 5;
    const int warp_m = wid >> 2;
    const int warp_n = wid & 3;
    const int bI = (int)(blk & 31);
    const int bO = (int)(blk >> 5);

    const uint32_t FULL  = sb;
    const uint32_t EMPTY = sb + 32;
    const uint32_t STG0  = sb + 1024;

    if (tid == 0) {
        for (int s = 0; s < 3; s++) {
            MBARRIER_INIT(FULL  + 8 * s, 1);
            MBARRIER_INIT(EMPTY + 8 * s, 8);
        }
    }
    __syncthreads();

    const char* bhsrc = (const char*)g_bh  + (size_t)bO * 4 * 16384;
    const char* ahsrc = (const char*)g_ahT + (size_t)bI * 4 * 16384;

    if (tid == 0) {
#pragma unroll
        for (int s = 0; s < 3; s++) {
            const uint32_t base = STG0 + s * WSTG_B;
            MBARRIER_EXPECT_TX(FULL + 8 * s, WSTG_B);
            bulk_g2s(base,         bhsrc + (size_t)s * 16384, 16384, FULL + 8 * s);
            bulk_g2s(base + 16384, ahsrc + (size_t)s * 16384, 16384, FULL + 8 * s);
        }
    }

    const int a_row      = warp_m * 64 + (lane & 15);
    const uint32_t a_rb  = (uint32_t)a_row * 128;
    const uint32_t amsk  = (uint32_t)(lane & 7) << 4;
    const uint32_t acol0 = (uint32_t)(lane >> 4) * 16;

    const int b_rowl     = warp_n * 32 + (lane & 7) + ((lane >> 4) & 1) * 8;
    const uint32_t b_rb  = (uint32_t)b_rowl * 128;
    const uint32_t bmsk  = (uint32_t)(lane & 7) << 4;
    const uint32_t bcol0 = (uint32_t)((lane >> 3) & 1) * 16;

    float acc[4][4][4];
#pragma unroll
    for (int i = 0; i < 4; i++)
#pragma unroll
        for (int t = 0; t < 4; t++)
#pragma unroll
            for (int q = 0; q < 4; q++) acc[i][t][q] = 0.0f;

#pragma unroll 1
    for (int it = 0; it < 4; ++it) {
        const int s  = it % 3;
        const int ph = (it / 3) & 1;
        WAIT_PARITY(FULL + 8 * s, ph);
        const uint32_t XA = STG0 + s * WSTG_B;
        const uint32_t WB = XA + 16384;
#pragma unroll
        for (int ks = 0; ks < 4; ks++) {
            const uint32_t acsw = (acol0 + ks * 32) ^ amsk;
            const uint32_t bcsw = (bcol0 + ks * 32) ^ bmsk;
            uint32_t A[4][4], B[2][4];
#pragma unroll
            for (int i = 0; i < 4; i++)
                LDSM_X4(A[i], XA + a_rb + i * 2048 + acsw);
#pragma unroll
            for (int j = 0; j < 2; j++)
                LDSM_X4(B[j], WB + b_rb + j * 2048 + bcsw);
#pragma unroll
            for (int i = 0; i < 4; i++)
#pragma unroll
                for (int j = 0; j < 2; j++) {
                    MMA16816(acc[i][2 * j],     A[i], B[j][0], B[j][1]);
                    MMA16816(acc[i][2 * j + 1], A[i], B[j][2], B[j][3]);
                }
        }
        __syncwarp();
        if (lane == 0) MBARRIER_ARRIVE(EMPTY + 8 * s);
        if (tid == 0 && it + 3 < 4) {
            WAIT_PARITY(EMPTY + 8 * s, ph);
            const int nk = it + 3;
            const uint32_t base = STG0 + s * WSTG_B;
            MBARRIER_EXPECT_TX(FULL + 8 * s, WSTG_B);
            bulk_g2s(base,         bhsrc + (size_t)nk * 16384, 16384, FULL + 8 * s);
            bulk_g2s(base + 16384, ahsrc + (size_t)nk * 16384, 16384, FULL + 8 * s);
        }
    }

    const int trow0 = warp_m * 64 + (lane >> 2);
    const int col0  = warp_n * 32 + (lane & 3) * 2;

#pragma unroll
    for (int t = 0; t < 4; t++) {
        const int col = col0 + t * 8;
        const int ig  = bI * 128 + col;
        const size_t tile = ((size_t)bO * 64 + (ig >> 6)) * 16384;
        const uint32_t cu2 = (uint32_t)(ig & 63) * 2;
#pragma unroll
        for (int i = 0; i < 4; i++) {
            const int r0 = trow0 + i * 16;
            const float2 w0 = *(const float2*)&W[(size_t)(bO * 128 + r0) * IN_DIM + ig];
            const float2 w1 = *(const float2*)&W[(size_t)(bO * 128 + r0 + 8) * IN_DIM + ig];
            const uint32_t v0 = h2u(__float2half_rn(w0.x + acc[i][t][0]),
                                    __float2half_rn(w0.y + acc[i][t][1]));
            const uint32_t v1 = h2u(__float2half_rn(w1.x + acc[i][t][2]),
                                    __float2half_rn(w1.y + acc[i][t][3]));
            *(uint32_t*)((char*)g_whi + tile + sw128((uint32_t)r0 * 128 + cu2))       = v0;
            *(uint32_t*)((char*)g_whi + tile + sw128((uint32_t)(r0 + 8) * 128 + cu2)) = v1;
        }
    }
}

// ---------------------------------------------------------------------------
// Kernel 3: PERSISTENT mma.sync mainloop (R7-exact).
//   grid = 148, block = 256 (8 warps, 2M x 4N, 64x64 warp tiles).
//   Stage s refilled by lane 0 of warp s (stage-distributed refill).
// ---------------------------------------------------------------------------
#define STAGES    4
#define STAGE_B   49152
#define SMEM_MAIN (1024 + STAGES * STAGE_B)

__global__ __launch_bounds__(256, 1) void vera_mma_main(
    const float* __restrict__ bias, float* __restrict__ y)
{
    extern __shared__ char smem[];
    const uint32_t sb = smem_u32(smem);
    const int tid  = threadIdx.x;
    const int lane = tid & 31;
    const int wid  = tid >> 5;
    const int bid  = blockIdx.x;

    const uint32_t FULL  = sb;
    const uint32_t EMPTY = sb + 32;
    const uint32_t STG0  = sb + 1024;

    if (tid == 0) {
        for (int s = 0; s < STAGES; s++) {
            MBARRIER_INIT(FULL  + 8 * s, 1);
            MBARRIER_INIT(EMPTY + 8 * s, 8);
        }
    }
    __syncthreads();

    const int ntile = (NTILES - 1 - bid) / NSM + 1;   // 6 or 7
    const int NITER = ntile * 64;

    // prologue fills (first tile, k = 0..3) — warp s fills stage s
    if (lane == 0 && wid < STAGES) {
        const int s = wid;
        const char* xs = (const char*)g_xhi + (size_t)((bid >> 4) * 64 + s) * 16384;
        const char* ws = (const char*)g_whi + (size_t)((bid & 15) * 2 * 64 + s) * 16384;
        const uint32_t base = STG0 + s * STAGE_B;
        MBARRIER_EXPECT_TX(FULL + 8 * s, STAGE_B);
        bulk_g2s(base,         xs, 16384, FULL + 8 * s);
        bulk_g2s(base + 16384, ws, 16384, FULL + 8 * s);
        bulk_g2s(base + 32768, ws + (size_t)64 * 16384, 16384, FULL + 8 * s);
    }

    const int warp_m = wid >> 2;
    const int warp_n = wid & 3;

    const int a_row      = warp_m * 64 + (lane & 15);
    const uint32_t a_rb  = (uint32_t)a_row * 128;
    const uint32_t amsk  = (uint32_t)(lane & 7) << 4;
    const uint32_t acol0 = (uint32_t)(lane >> 4) * 16;

    const int b_rowl     = (warp_n & 1) * 64 + (lane & 7) + ((lane >> 4) & 1) * 8;
    const uint32_t b_rb  = (uint32_t)((warp_n >> 1) * 16384 + b_rowl * 128);
    const uint32_t bmsk  = (uint32_t)(lane & 7) << 4;
    const uint32_t bcol0 = (uint32_t)((lane >> 3) & 1) * 16;

    float acc[4][8][4];
#pragma unroll
    for (int i = 0; i < 4; i++)
#pragma unroll
        for (int t = 0; t < 8; t++)
#pragma unroll
            for (int q = 0; q < 4; q++) acc[i][t][q] = 0.0f;

#pragma unroll 1
    for (int p = 0; p < NITER; ++p) {
        const int s  = p & 3;
        const int ph = (p >> 2) & 1;
        WAIT_PARITY(FULL + 8 * s, ph);
        const uint32_t XA = STG0 + s * STAGE_B;
        const uint32_t WB = XA + 16384;

#pragma unroll
        for (int ks = 0; ks < 4; ks++) {
            const uint32_t acsw = (acol0 + ks * 32) ^ amsk;
            const uint32_t bcsw = (bcol0 + ks * 32) ^ bmsk;
            uint32_t A[4][4], B[4][4];
#pragma unroll
            for (int i = 0; i < 4; i++)
                LDSM_X4(A[i], XA + a_rb + i * 2048 + acsw);
#pragma unroll
            for (int j = 0; j < 4; j++)
                LDSM_X4(B[j], WB + b_rb + j * 2048 + bcsw);
#pragma unroll
            for (int i = 0; i < 4; i++)
#pragma unroll
                for (int j = 0; j < 4; j++) {
                    MMA16816(acc[i][2 * j],     A[i], B[j][0], B[j][1]);
                    MMA16816(acc[i][2 * j + 1], A[i], B[j][2], B[j][3]);
                }
        }

        __syncwarp();
        if (lane == 0) MBARRIER_ARRIVE(EMPTY + 8 * s);

        // stage-distributed refill: warp s owns stage s
        if (wid == s && lane == 0 && p + STAGES < NITER) {
            WAIT_PARITY(EMPTY + 8 * s, ph);
            const int q    = p + STAGES;
            const int tile = bid + (q >> 6) * NSM;
            const int k    = q & 63;
            const char* xs = (const char*)g_xhi + (size_t)((tile >> 4) * 64 + k) * 16384;
            const char* ws = (const char*)g_whi + (size_t)((tile & 15) * 2 * 64 + k) * 16384;
            const uint32_t base = STG0 + s * STAGE_B;
            MBARRIER_EXPECT_TX(FULL + 8 * s, STAGE_B);
            bulk_g2s(base,         xs, 16384, FULL + 8 * s);
            bulk_g2s(base + 16384, ws, 16384, FULL + 8 * s);
            bulk_g2s(base + 32768, ws + (size_t)64 * 16384, 16384, FULL + 8 * s);
        }

        // tile epilogue
        if ((p & 63) == 63) {
            const int tile = bid + (p >> 6) * NSM;
            const int bM = tile >> 4;
            const int bN = tile & 15;
            const int trow0 = bM * 128 + warp_m * 64 + (lane >> 2);
            const int col0g = bN * 256 + warp_n * 64 + (lane & 3) * 2;
#pragma unroll
            for (int t = 0; t < 8; t++) {
                const int col = col0g + t * 8;
                const float2 bv = *(const float2*)&bias[col];
#pragma unroll
                for (int i = 0; i < 4; i++) {
                    const int r0 = trow0 + i * 16;
                    float2 o0 = make_float2(acc[i][t][0] + bv.x, acc[i][t][1] + bv.y);
                    float2 o1 = make_float2(acc[i][t][2] + bv.x, acc[i][t][3] + bv.y);
                    *(float2*)&y[(size_t)r0 * OUT_DIM + col]       = o0;
                    *(float2*)&y[(size_t)(r0 + 8) * OUT_DIM + col] = o1;
                }
            }
#pragma unroll
            for (int i = 0; i < 4; i++)
#pragma unroll
                for (int t = 0; t < 8; t++)
#pragma unroll
                    for (int q = 0; q < 4; q++) acc[i][t][q] = 0.0f;
        }
    }
}

// ---------------------------------------------------------------------------
// Launch. Inputs: x, base_weight, base_bias, vera_random_A, vera_random_B,
//                 vera_d, vera_b
// ---------------------------------------------------------------------------
extern "C" void kernel_launch(void* const* d_in, const int* in_sizes, int n_in,
                              void* d_out, int out_size)
{
    const float* x    = (const float*)d_in[0];
    const float* W    = (const float*)d_in[1];
    const float* bias = (const float*)d_in[2];
    const float* vA   = (const float*)d_in[3];
    const float* vB   = (const float*)d_in[4];
    const float* vd   = (const float*)d_in[5];
    const float* vb   = (const float*)d_in[6];
    float* y = (float*)d_out;

    cudaFuncSetAttribute(vera_mid,
                         cudaFuncAttributeMaxDynamicSharedMemorySize, WSMEM);
    cudaFuncSetAttribute(vera_mma_main,
                         cudaFuncAttributeMaxDynamicSharedMemorySize, SMEM_MAIN);

    // 1. tiny operand conversion (Bh, AhT)
    vera_conv<<<1536, 256>>>(vB, vb, vA, vd);

    // 2. fused middle stage: weff HMMA (1024 blocks) || x convert (16384 blocks)
    vera_mid<<<1024 + 16384, 256, WSMEM>>>(x, W);

    // 3. persistent main GEMM
    vera_mma_main<<<NSM, 256, SMEM_MAIN>>>(bias, y);
}

// round 10
// speedup vs baseline: 1.0428x; 1.0428x over previous
#include <cuda_runtime.h>
#include <cuda_fp16.h>
#include <cstdint>

#define T_DIM   8192
#define IN_DIM  4096
#define OUT_DIM 4096
#define R_DIM   256
#define SCALE_F 4.0f
#define NSM     148
#define NTILES  1024   /* 16 (o/256) x 64 (t/128) */

// Tiled + SW128-pre-swizzled fp16 operand buffers (16KB tiles: 128 rows x 64 cols)
__device__ __align__(128) __half g_xhi[(size_t)T_DIM  * IN_DIM];
__device__ __align__(128) __half g_whi[(size_t)OUT_DIM * IN_DIM];
__device__ __align__(128) __half g_bh [(size_t)OUT_DIM * R_DIM];
__device__ __align__(128) __half g_ahT[(size_t)IN_DIM  * R_DIM];

// ---------------------------------------------------------------------------
// helpers
// ---------------------------------------------------------------------------
static __device__ __forceinline__ uint32_t sw128(uint32_t b) {
    return b ^ ((b >> 3) & 0x70);
}
static __device__ __forceinline__ uint32_t smem_u32(const void* p) {
    uint32_t a;
    asm("{ .reg .u64 t; cvta.to.shared.u64 t, %1; cvt.u32.u64 %0, t; }"
        : "=r"(a) : "l"(p));
    return a;
}
static __device__ __forceinline__ uint32_t h2u(__half a, __half b) {
    __half2 h = __halves2half2(a, b);
    return *(uint32_t*)&h;
}

#define MBARRIER_INIT(m, c) \
    asm volatile("mbarrier.init.shared.b64 [%0], %1;" :: "r"(m), "r"((uint32_t)(c)) : "memory")
#define MBARRIER_EXPECT_TX(m, b) \
    asm volatile("mbarrier.arrive.expect_tx.shared.b64 _, [%0], %1;" :: "r"(m), "r"((uint32_t)(b)) : "memory")
#define MBARRIER_ARRIVE(m) \
    asm volatile("mbarrier.arrive.shared.b64 _, [%0];" :: "r"(m) : "memory")

#define WAIT_PARITY(m, p) do {                                                    \
    uint32_t _m = (m), _p = (uint32_t)(p), _d;                                    \
    asm volatile("{\n\t.reg .pred P;\n\t"                                         \
        "mbarrier.try_wait.parity.acquire.cta.shared::cta.b64 P, [%1], %2;\n\t"   \
        "selp.b32 %0, 1, 0, P;\n\t}" : "=r"(_d) : "r"(_m), "r"(_p) : "memory");   \
    while (!_d) {                                                                 \
        asm volatile("{\n\t.reg .pred P;\n\t"                                     \
            "mbarrier.try_wait.parity.acquire.cta.shared::cta.b64 P, [%1], %2, 0x989680;\n\t" \
            "selp.b32 %0, 1, 0, P;\n\t}" : "=r"(_d) : "r"(_m), "r"(_p) : "memory"); \
    } } while (0)

static __device__ __forceinline__ void bulk_g2s(uint32_t dst, const void* src,
                                                uint32_t bytes, uint32_t mbar) {
    unsigned long long g = (unsigned long long)__cvta_generic_to_global(src);
    asm volatile("cp.async.bulk.shared::cta.global.mbarrier::complete_tx::bytes [%0], [%1], %2, [%3];"
                 :: "r"(dst), "l"(g), "r"(bytes), "r"(mbar) : "memory");
}

#define LDSM_X4(r, addr) \
    asm volatile("ldmatrix.sync.aligned.m8n8.x4.shared.b16 {%0,%1,%2,%3}, [%4];" \
                 : "=r"((r)[0]), "=r"((r)[1]), "=r"((r)[2]), "=r"((r)[3]) : "r"(addr))

#define MMA16816(c, a, b0, b1) \
    asm volatile("mma.sync.aligned.m16n8k16.row.col.f32.f16.f16.f32 " \
                 "{%0,%1,%2,%3}, {%4,%5,%6,%7}, {%8,%9}, {%0,%1,%2,%3};" \
                 : "+f"((c)[0]), "+f"((c)[1]), "+f"((c)[2]), "+f"((c)[3]) \
                 : "r"((a)[0]), "r"((a)[1]), "r"((a)[2]), "r"((a)[3]), \
                   "r"(b0), "r"(b1))

// ---------------------------------------------------------------------------
// Kernel 1a: tiny conv — Bh and AhT fp16 tiles (precedes weff, default stream)
// ---------------------------------------------------------------------------
__global__ __launch_bounds__(256) void vera_conv(
    const float* __restrict__ vB, const float* __restrict__ vb,
    const float* __restrict__ vA, const float* __restrict__ vd)
{
    const uint32_t blk = blockIdx.x;
    if (blk < 512) {
        // Bh = fp16( (SCALE/64) * b[o] * vB[o][r] )
        const uint32_t c    = blk * 256 + threadIdx.x;
        const uint32_t o    = c >> 5;
        const uint32_t r8   = c & 31;
        const uint32_t rblk = r8 >> 3;
        const uint32_t cu   = (r8 & 7) * 8;

        const float s = __ldg(&vb[o]) * (SCALE_F / 64.0f);
        const float* src = vB + (size_t)o * R_DIM + rblk * 64 + cu;
        float4 a = *(const float4*)src;
        float4 b = *(const float4*)(src + 4);
        __half h[8] = {__float2half_rn(a.x * s), __float2half_rn(a.y * s),
                       __float2half_rn(a.z * s), __float2half_rn(a.w * s),
                       __float2half_rn(b.x * s), __float2half_rn(b.y * s),
                       __float2half_rn(b.z * s), __float2half_rn(b.w * s)};
        uint4 v = make_uint4(h2u(h[0], h[1]), h2u(h[2], h[3]),
                             h2u(h[4], h[5]), h2u(h[6], h[7]));
        const size_t tile = ((size_t)(o >> 7) * 4 + rblk) * 16384;
        const uint32_t off = sw128((o & 127) * 128 + cu * 2);
        *(uint4*)((char*)g_bh + tile + off) = v;
    } else {
        // AhT[i][r] = fp16( 64 * d[r] * vA[r][i] )  (transpose)
        const uint32_t c  = (blk - 512) * 256 + threadIdx.x;
        const uint32_t r  = c >> 10;
        const uint32_t i4 = (c & 1023) * 4;

        const float s = __ldg(&vd[r]) * 64.0f;
        float4 v = *(const float4*)&vA[(size_t)r * IN_DIM + i4];
        const float vv[4] = {v.x, v.y, v.z, v.w};
#pragma unroll
        for (int j = 0; j < 4; j++) {
            const uint32_t i = i4 + j;
            const size_t tile = ((size_t)(i >> 7) * 4 + (r >> 6)) * 16384;
            const uint32_t off = sw128((i & 127) * 128 + (r & 63) * 2);
            *(__half*)((char*)g_ahT + tile + off) = __float2half_rn(vv[j] * s);
        }
    }
}

// ---------------------------------------------------------------------------
// Kernel 1b: x -> fp16 tiles (independent branch, side stream, full occupancy)
// ---------------------------------------------------------------------------
__global__ __launch_bounds__(256) void vera_xprep(const float* __restrict__ x)
{
    const uint32_t c    = blockIdx.x * 256 + threadIdx.x;
    const uint32_t k8   = c & 511;
    const uint32_t t    = c >> 9;
    const uint32_t kblk = k8 >> 3;
    const uint32_t cu   = (k8 & 7) * 8;
    const uint32_t row  = t & 127;
    const uint32_t mblk = t >> 7;

    const float* src = x + (size_t)t * IN_DIM + kblk * 64 + cu;
    float4 a = *(const float4*)src;
    float4 b = *(const float4*)(src + 4);
    __half2 p0 = __floats2half2_rn(a.x, a.y);
    __half2 p1 = __floats2half2_rn(a.z, a.w);
    __half2 p2 = __floats2half2_rn(b.x, b.y);
    __half2 p3 = __floats2half2_rn(b.z, b.w);
    uint4 v = make_uint4(*(uint32_t*)&p0, *(uint32_t*)&p1,
                         *(uint32_t*)&p2, *(uint32_t*)&p3);
    const uint32_t off = sw128(row * 128 + cu * 2);
    *(uint4*)((char*)g_xhi + ((size_t)mblk * 64 + kblk) * 16384 + off) = v;
}

// ---------------------------------------------------------------------------
// Kernel 2: Weff via HMMA: M=128(o) x N=128(i), K=256, 3-stage, 2 CTA/SM.
// ---------------------------------------------------------------------------
#define WSTG_B  32768
#define WSMEM   (1024 + 3 * WSTG_B)

__global__ __launch_bounds__(256, 2) void vera_weff_mma(const float* __restrict__ W)
{
    extern __shared__ char smem[];
    const uint32_t sb = smem_u32(smem);
    const int tid  = threadIdx.x;
    const int lane = tid & 31;
    const int wid  = tid >> 5;
    const int warp_m = wid >> 2;
    const int warp_n = wid & 3;
    const int bI = blockIdx.x;
    const int bO = blockIdx.y;

    const uint32_t FULL  = sb;
    const uint32_t EMPTY = sb + 32;
    const uint32_t STG0  = sb + 1024;

    if (tid == 0) {
        for (int s = 0; s < 3; s++) {
            MBARRIER_INIT(FULL  + 8 * s, 1);
            MBARRIER_INIT(EMPTY + 8 * s, 8);
        }
    }
    __syncthreads();

    const char* bhsrc = (const char*)g_bh  + (size_t)bO * 4 * 16384;
    const char* ahsrc = (const char*)g_ahT + (size_t)bI * 4 * 16384;

    if (tid == 0) {
#pragma unroll
        for (int s = 0; s < 3; s++) {
            const uint32_t base = STG0 + s * WSTG_B;
            MBARRIER_EXPECT_TX(FULL + 8 * s, WSTG_B);
            bulk_g2s(base,         bhsrc + (size_t)s * 16384, 16384, FULL + 8 * s);
            bulk_g2s(base + 16384, ahsrc + (size_t)s * 16384, 16384, FULL + 8 * s);
        }
    }

    const int a_row      = warp_m * 64 + (lane & 15);
    const uint32_t a_rb  = (uint32_t)a_row * 128;
    const uint32_t amsk  = (uint32_t)(lane & 7) << 4;
    const uint32_t acol0 = (uint32_t)(lane >> 4) * 16;

    const int b_rowl     = warp_n * 32 + (lane & 7) + ((lane >> 4) & 1) * 8;
    const uint32_t b_rb  = (uint32_t)b_rowl * 128;
    const uint32_t bmsk  = (uint32_t)(lane & 7) << 4;
    const uint32_t bcol0 = (uint32_t)((lane >> 3) & 1) * 16;

    float acc[4][4][4];
#pragma unroll
    for (int i = 0; i < 4; i++)
#pragma unroll
        for (int t = 0; t < 4; t++)
#pragma unroll
            for (int q = 0; q < 4; q++) acc[i][t][q] = 0.0f;

#pragma unroll 1
    for (int it = 0; it < 4; ++it) {
        const int s  = it % 3;
        const int ph = (it / 3) & 1;
        WAIT_PARITY(FULL + 8 * s, ph);
        const uint32_t XA = STG0 + s * WSTG_B;
        const uint32_t WB = XA + 16384;
#pragma unroll
        for (int ks = 0; ks < 4; ks++) {
            const uint32_t acsw = (acol0 + ks * 32) ^ amsk;
            const uint32_t bcsw = (bcol0 + ks * 32) ^ bmsk;
            uint32_t A[4][4], B[2][4];
#pragma unroll
            for (int i = 0; i < 4; i++)
                LDSM_X4(A[i], XA + a_rb + i * 2048 + acsw);
#pragma unroll
            for (int j = 0; j < 2; j++)
                LDSM_X4(B[j], WB + b_rb + j * 2048 + bcsw);
#pragma unroll
            for (int i = 0; i < 4; i++)
#pragma unroll
                for (int j = 0; j < 2; j++) {
                    MMA16816(acc[i][2 * j],     A[i], B[j][0], B[j][1]);
                    MMA16816(acc[i][2 * j + 1], A[i], B[j][2], B[j][3]);
                }
        }
        __syncwarp();
        if (lane == 0) MBARRIER_ARRIVE(EMPTY + 8 * s);
        if (tid == 0 && it + 3 < 4) {
            WAIT_PARITY(EMPTY + 8 * s, ph);
            const int nk = it + 3;
            const uint32_t base = STG0 + s * WSTG_B;
            MBARRIER_EXPECT_TX(FULL + 8 * s, WSTG_B);
            bulk_g2s(base,         bhsrc + (size_t)nk * 16384, 16384, FULL + 8 * s);
            bulk_g2s(base + 16384, ahsrc + (size_t)nk * 16384, 16384, FULL + 8 * s);
        }
    }

    const int trow0 = warp_m * 64 + (lane >> 2);
    const int col0  = warp_n * 32 + (lane & 3) * 2;

#pragma unroll
    for (int t = 0; t < 4; t++) {
        const int col = col0 + t * 8;
        const int ig  = bI * 128 + col;
        const size_t tile = ((size_t)bO * 64 + (ig >> 6)) * 16384;
        const uint32_t cu2 = (uint32_t)(ig & 63) * 2;
#pragma unroll
        for (int i = 0; i < 4; i++) {
            const int r0 = trow0 + i * 16;
            const float2 w0 = *(const float2*)&W[(size_t)(bO * 128 + r0) * IN_DIM + ig];
            const float2 w1 = *(const float2*)&W[(size_t)(bO * 128 + r0 + 8) * IN_DIM + ig];
            const uint32_t v0 = h2u(__float2half_rn(w0.x + acc[i][t][0]),
                                    __float2half_rn(w0.y + acc[i][t][1]));
            const uint32_t v1 = h2u(__float2half_rn(w1.x + acc[i][t][2]),
                                    __float2half_rn(w1.y + acc[i][t][3]));
            *(uint32_t*)((char*)g_whi + tile + sw128((uint32_t)r0 * 128 + cu2))       = v0;
            *(uint32_t*)((char*)g_whi + tile + sw128((uint32_t)(r0 + 8) * 128 + cu2)) = v1;
        }
    }
}

// ---------------------------------------------------------------------------
// Kernel 3: PERSISTENT mma.sync mainloop (R7-exact).
//   grid = 148, block = 256 (8 warps, 2M x 4N, 64x64 warp tiles).
//   Stage s refilled by lane 0 of warp s (stage-distributed refill).
// ---------------------------------------------------------------------------
#define STAGES    4
#define STAGE_B   49152
#define SMEM_MAIN (1024 + STAGES * STAGE_B)

__global__ __launch_bounds__(256, 1) void vera_mma_main(
    const float* __restrict__ bias, float* __restrict__ y)
{
    extern __shared__ char smem[];
    const uint32_t sb = smem_u32(smem);
    const int tid  = threadIdx.x;
    const int lane = tid & 31;
    const int wid  = tid >> 5;
    const int bid  = blockIdx.x;

    const uint32_t FULL  = sb;
    const uint32_t EMPTY = sb + 32;
    const uint32_t STG0  = sb + 1024;

    if (tid == 0) {
        for (int s = 0; s < STAGES; s++) {
            MBARRIER_INIT(FULL  + 8 * s, 1);
            MBARRIER_INIT(EMPTY + 8 * s, 8);
        }
    }
    __syncthreads();

    const int ntile = (NTILES - 1 - bid) / NSM + 1;   // 6 or 7
    const int NITER = ntile * 64;

    // prologue fills (first tile, k = 0..3) — warp s fills stage s
    if (lane == 0 && wid < STAGES) {
        const int s = wid;
        const char* xs = (const char*)g_xhi + (size_t)((bid >> 4) * 64 + s) * 16384;
        const char* ws = (const char*)g_whi + (size_t)((bid & 15) * 2 * 64 + s) * 16384;
        const uint32_t base = STG0 + s * STAGE_B;
        MBARRIER_EXPECT_TX(FULL + 8 * s, STAGE_B);
        bulk_g2s(base,         xs, 16384, FULL + 8 * s);
        bulk_g2s(base + 16384, ws, 16384, FULL + 8 * s);
        bulk_g2s(base + 32768, ws + (size_t)64 * 16384, 16384, FULL + 8 * s);
    }

    const int warp_m = wid >> 2;
    const int warp_n = wid & 3;

    const int a_row      = warp_m * 64 + (lane & 15);
    const uint32_t a_rb  = (uint32_t)a_row * 128;
    const uint32_t amsk  = (uint32_t)(lane & 7) << 4;
    const uint32_t acol0 = (uint32_t)(lane >> 4) * 16;

    const int b_rowl     = (warp_n & 1) * 64 + (lane & 7) + ((lane >> 4) & 1) * 8;
    const uint32_t b_rb  = (uint32_t)((warp_n >> 1) * 16384 + b_rowl * 128);
    const uint32_t bmsk  = (uint32_t)(lane & 7) << 4;
    const uint32_t bcol0 = (uint32_t)((lane >> 3) & 1) * 16;

    float acc[4][8][4];
#pragma unroll
    for (int i = 0; i < 4; i++)
#pragma unroll
        for (int t = 0; t < 8; t++)
#pragma unroll
            for (int q = 0; q < 4; q++) acc[i][t][q] = 0.0f;

#pragma unroll 1
    for (int p = 0; p < NITER; ++p) {
        const int s  = p & 3;
        const int ph = (p >> 2) & 1;
        WAIT_PARITY(FULL + 8 * s, ph);
        const uint32_t XA = STG0 + s * STAGE_B;
        const uint32_t WB = XA + 16384;

#pragma unroll
        for (int ks = 0; ks < 4; ks++) {
            const uint32_t acsw = (acol0 + ks * 32) ^ amsk;
            const uint32_t bcsw = (bcol0 + ks * 32) ^ bmsk;
            uint32_t A[4][4], B[4][4];
#pragma unroll
            for (int i = 0; i < 4; i++)
                LDSM_X4(A[i], XA + a_rb + i * 2048 + acsw);
#pragma unroll
            for (int j = 0; j < 4; j++)
                LDSM_X4(B[j], WB + b_rb + j * 2048 + bcsw);
#pragma unroll
            for (int i = 0; i < 4; i++)
#pragma unroll
                for (int j = 0; j < 4; j++) {
                    MMA16816(acc[i][2 * j],     A[i], B[j][0], B[j][1]);
                    MMA16816(acc[i][2 * j + 1], A[i], B[j][2], B[j][3]);
                }
        }

        __syncwarp();
        if (lane == 0) MBARRIER_ARRIVE(EMPTY + 8 * s);

        // stage-distributed refill: warp s owns stage s
        if (wid == s && lane == 0 && p + STAGES < NITER) {
            WAIT_PARITY(EMPTY + 8 * s, ph);
            const int q    = p + STAGES;
            const int tile = bid + (q >> 6) * NSM;
            const int k    = q & 63;
            const char* xs = (const char*)g_xhi + (size_t)((tile >> 4) * 64 + k) * 16384;
            const char* ws = (const char*)g_whi + (size_t)((tile & 15) * 2 * 64 + k) * 16384;
            const uint32_t base = STG0 + s * STAGE_B;
            MBARRIER_EXPECT_TX(FULL + 8 * s, STAGE_B);
            bulk_g2s(base,         xs, 16384, FULL + 8 * s);
            bulk_g2s(base + 16384, ws, 16384, FULL + 8 * s);
            bulk_g2s(base + 32768, ws + (size_t)64 * 16384, 16384, FULL + 8 * s);
        }

        // tile epilogue
        if ((p & 63) == 63) {
            const int tile = bid + (p >> 6) * NSM;
            const int bM = tile >> 4;
            const int bN = tile & 15;
            const int trow0 = bM * 128 + warp_m * 64 + (lane >> 2);
            const int col0g = bN * 256 + warp_n * 64 + (lane & 3) * 2;
#pragma unroll
            for (int t = 0; t < 8; t++) {
                const int col = col0g + t * 8;
                const float2 bv = *(const float2*)&bias[col];
#pragma unroll
                for (int i = 0; i < 4; i++) {
                    const int r0 = trow0 + i * 16;
                    float2 o0 = make_float2(acc[i][t][0] + bv.x, acc[i][t][1] + bv.y);
                    float2 o1 = make_float2(acc[i][t][2] + bv.x, acc[i][t][3] + bv.y);
                    *(float2*)&y[(size_t)r0 * OUT_DIM + col]       = o0;
                    *(float2*)&y[(size_t)(r0 + 8) * OUT_DIM + col] = o1;
                }
            }
#pragma unroll
            for (int i = 0; i < 4; i++)
#pragma unroll
                for (int t = 0; t < 8; t++)
#pragma unroll
                    for (int q = 0; q < 4; q++) acc[i][t][q] = 0.0f;
        }
    }
}

// ---------------------------------------------------------------------------
// Launch. Inputs: x, base_weight, base_bias, vera_random_A, vera_random_B,
//                 vera_d, vera_b
//
// Graph shape (fork-join, capture-legal):
//      default:  conv ─ weff ──────────┐
//                  \                    ├─ join ─ main
//      side:        └ xprep ───────────┘
// ---------------------------------------------------------------------------
extern "C" void kernel_launch(void* const* d_in, const int* in_sizes, int n_in,
                              void* d_out, int out_size)
{
    const float* x    = (const float*)d_in[0];
    const float* W    = (const float*)d_in[1];
    const float* bias = (const float*)d_in[2];
    const float* vA   = (const float*)d_in[3];
    const float* vB   = (const float*)d_in[4];
    const float* vd   = (const float*)d_in[5];
    const float* vb   = (const float*)d_in[6];
    float* y = (float*)d_out;

    // One-time handle creation (host resources only; the captured work is
    // identical on every call).
    static cudaStream_t s_side = nullptr;
    static cudaEvent_t  e_fork = nullptr, e_join = nullptr;
    if (s_side == nullptr) {
        cudaStreamCreateWithFlags(&s_side, cudaStreamNonBlocking);
        cudaEventCreateWithFlags(&e_fork, cudaEventDisableTiming);
        cudaEventCreateWithFlags(&e_join, cudaEventDisableTiming);
        cudaFuncSetAttribute(vera_weff_mma,
                             cudaFuncAttributeMaxDynamicSharedMemorySize, WSMEM);
        cudaFuncSetAttribute(vera_mma_main,
                             cudaFuncAttributeMaxDynamicSharedMemorySize, SMEM_MAIN);
    }

    // fork: side stream runs x conversion concurrently with conv+weff
    cudaEventRecord(e_fork, 0);
    cudaStreamWaitEvent(s_side, e_fork, 0);
    vera_xprep<<<16384, 256, 0, s_side>>>(x);
    cudaEventRecord(e_join, s_side);

    // default stream: Bh/AhT conversion, then weff HMMA
    vera_conv<<<1536, 256>>>(vB, vb, vA, vd);
    dim3 gweff(IN_DIM / 128, OUT_DIM / 128);   // 32 x 32
    vera_weff_mma<<<gweff, 256, WSMEM>>>(W);

    // join, then persistent main GEMM
    cudaStreamWaitEvent(0, e_join, 0);
    vera_mma_main<<<NSM, 256, SMEM_MAIN>>>(bias, y);
}

// round 11
// speedup vs baseline: 1.0574x; 1.0140x over previous
#include <cuda_runtime.h>
#include <cuda_fp16.h>
#include <cstdint>

#define T_DIM   8192
#define IN_DIM  4096
#define OUT_DIM 4096
#define R_DIM   256
#define SCALE_F 4.0f
#define NSM     148
#define NTILES  1024   /* 16 (o/256) x 64 (t/128) */

// Tiled + SW128-pre-swizzled fp16 operand buffers (16KB tiles: 128 rows x 64 cols)
__device__ __align__(128) __half g_xhi[(size_t)T_DIM  * IN_DIM];
__device__ __align__(128) __half g_whi[(size_t)OUT_DIM * IN_DIM];
__device__ __align__(128) __half g_bh [(size_t)OUT_DIM * R_DIM];
__device__ __align__(128) __half g_ahT[(size_t)IN_DIM  * R_DIM];

// ---------------------------------------------------------------------------
// helpers
// ---------------------------------------------------------------------------
static __device__ __forceinline__ uint32_t sw128(uint32_t b) {
    return b ^ ((b >> 3) & 0x70);
}
static __device__ __forceinline__ uint32_t smem_u32(const void* p) {
    uint32_t a;
    asm("{ .reg .u64 t; cvta.to.shared.u64 t, %1; cvt.u32.u64 %0, t; }"
        : "=r"(a) : "l"(p));
    return a;
}
static __device__ __forceinline__ uint32_t h2u(__half a, __half b) {
    __half2 h = __halves2half2(a, b);
    return *(uint32_t*)&h;
}

#define MBARRIER_INIT(m, c) \
    asm volatile("mbarrier.init.shared.b64 [%0], %1;" :: "r"(m), "r"((uint32_t)(c)) : "memory")
#define MBARRIER_EXPECT_TX(m, b) \
    asm volatile("mbarrier.arrive.expect_tx.shared.b64 _, [%0], %1;" :: "r"(m), "r"((uint32_t)(b)) : "memory")
#define MBARRIER_ARRIVE(m) \
    asm volatile("mbarrier.arrive.shared.b64 _, [%0];" :: "r"(m) : "memory")

#define WAIT_PARITY(m, p) do {                                                    \
    uint32_t _m = (m), _p = (uint32_t)(p), _d;                                    \
    asm volatile("{\n\t.reg .pred P;\n\t"                                         \
        "mbarrier.try_wait.parity.acquire.cta.shared::cta.b64 P, [%1], %2;\n\t"   \
        "selp.b32 %0, 1, 0, P;\n\t}" : "=r"(_d) : "r"(_m), "r"(_p) : "memory");   \
    while (!_d) {                                                                 \
        asm volatile("{\n\t.reg .pred P;\n\t"                                     \
            "mbarrier.try_wait.parity.acquire.cta.shared::cta.b64 P, [%1], %2, 0x989680;\n\t" \
            "selp.b32 %0, 1, 0, P;\n\t}" : "=r"(_d) : "r"(_m), "r"(_p) : "memory"); \
    } } while (0)

static __device__ __forceinline__ void bulk_g2s(uint32_t dst, const void* src,
                                                uint32_t bytes, uint32_t mbar) {
    unsigned long long g = (unsigned long long)__cvta_generic_to_global(src);
    asm volatile("cp.async.bulk.shared::cta.global.mbarrier::complete_tx::bytes [%0], [%1], %2, [%3];"
                 :: "r"(dst), "l"(g), "r"(bytes), "r"(mbar) : "memory");
}

#define LDSM_X4(r, addr) \
    asm volatile("ldmatrix.sync.aligned.m8n8.x4.shared.b16 {%0,%1,%2,%3}, [%4];" \
                 : "=r"((r)[0]), "=r"((r)[1]), "=r"((r)[2]), "=r"((r)[3]) : "r"(addr))

#define MMA16816(c, a, b0, b1) \
    asm volatile("mma.sync.aligned.m16n8k16.row.col.f32.f16.f16.f32 " \
                 "{%0,%1,%2,%3}, {%4,%5,%6,%7}, {%8,%9}, {%0,%1,%2,%3};" \
                 : "+f"((c)[0]), "+f"((c)[1]), "+f"((c)[2]), "+f"((c)[3]) \
                 : "r"((a)[0]), "r"((a)[1]), "r"((a)[2]), "r"((a)[3]), \
                   "r"(b0), "r"(b1))

// ---------------------------------------------------------------------------
// Kernel 1a: conv — Bh (vectorized) and AhT (coalesced-read transpose,
// vectorized 16B stores). Default stream; precedes weff.
//   blocks [0,512)    : Bh
//   blocks [512,1024) : AhT v2
// ---------------------------------------------------------------------------
__global__ __launch_bounds__(256) void vera_conv(
    const float* __restrict__ vB, const float* __restrict__ vb,
    const float* __restrict__ vA, const float* __restrict__ vd)
{
    const uint32_t blk = blockIdx.x;
    if (blk < 512) {
        // Bh = fp16( (SCALE/64) * b[o] * vB[o][r] )
        const uint32_t c    = blk * 256 + threadIdx.x;
        const uint32_t o    = c >> 5;
        const uint32_t r8   = c & 31;
        const uint32_t rblk = r8 >> 3;
        const uint32_t cu   = (r8 & 7) * 8;

        const float s = __ldg(&vb[o]) * (SCALE_F / 64.0f);
        const float* src = vB + (size_t)o * R_DIM + rblk * 64 + cu;
        float4 a = *(const float4*)src;
        float4 b = *(const float4*)(src + 4);
        __half h[8] = {__float2half_rn(a.x * s), __float2half_rn(a.y * s),
                       __float2half_rn(a.z * s), __float2half_rn(a.w * s),
                       __float2half_rn(b.x * s), __float2half_rn(b.y * s),
                       __float2half_rn(b.z * s), __float2half_rn(b.w * s)};
        uint4 v = make_uint4(h2u(h[0], h[1]), h2u(h[2], h[3]),
                             h2u(h[4], h[5]), h2u(h[6], h[7]));
        const size_t tile = ((size_t)(o >> 7) * 4 + rblk) * 16384;
        const uint32_t off = sw128((o & 127) * 128 + cu * 2);
        *(uint4*)((char*)g_bh + tile + off) = v;
    } else {
        // AhT[i][r] = fp16( 64 * d[r] * vA[r][i] )
        // thread owns (i, 8 consecutive r). Loads coalesced over i,
        // result packed into ONE uint4 store (row i, col chunk r8).
        const uint32_t c  = (blk - 512) * 256 + threadIdx.x;  // 131072 threads
        const uint32_t r8 = c >> 12;          // 0..31  (chunk of 8 r)
        const uint32_t i  = c & 4095;         // coalesced within warp

        uint32_t pk[4];
#pragma unroll
        for (int j = 0; j < 4; j++) {
            const uint32_t r0 = r8 * 8 + 2 * j;
            const float s0 = __ldg(&vd[r0])     * 64.0f;
            const float s1 = __ldg(&vd[r0 + 1]) * 64.0f;
            const float v0 = __ldg(&vA[(size_t)r0 * IN_DIM + i])       * s0;
            const float v1 = __ldg(&vA[(size_t)(r0 + 1) * IN_DIM + i]) * s1;
            pk[j] = h2u(__float2half_rn(v0), __float2half_rn(v1));
        }
        const size_t tile = ((size_t)(i >> 7) * 4 + (r8 >> 3)) * 16384;
        const uint32_t off = sw128((i & 127) * 128 + (r8 & 7) * 16);
        *(uint4*)((char*)g_ahT + tile + off) = make_uint4(pk[0], pk[1], pk[2], pk[3]);
    }
}

// ---------------------------------------------------------------------------
// Kernel 1b: x -> fp16 tiles (independent branch, side stream)
// ---------------------------------------------------------------------------
__global__ __launch_bounds__(256) void vera_xprep(const float* __restrict__ x)
{
    const uint32_t c    = blockIdx.x * 256 + threadIdx.x;
    const uint32_t k8   = c & 511;
    const uint32_t t    = c >> 9;
    const uint32_t kblk = k8 >> 3;
    const uint32_t cu   = (k8 & 7) * 8;
    const uint32_t row  = t & 127;
    const uint32_t mblk = t >> 7;

    const float* src = x + (size_t)t * IN_DIM + kblk * 64 + cu;
    float4 a = *(const float4*)src;
    float4 b = *(const float4*)(src + 4);
    __half2 p0 = __floats2half2_rn(a.x, a.y);
    __half2 p1 = __floats2half2_rn(a.z, a.w);
    __half2 p2 = __floats2half2_rn(b.x, b.y);
    __half2 p3 = __floats2half2_rn(b.z, b.w);
    uint4 v = make_uint4(*(uint32_t*)&p0, *(uint32_t*)&p1,
                         *(uint32_t*)&p2, *(uint32_t*)&p3);
    const uint32_t off = sw128(row * 128 + cu * 2);
    *(uint4*)((char*)g_xhi + ((size_t)mblk * 64 + kblk) * 16384 + off) = v;
}

// ---------------------------------------------------------------------------
// Kernel 2: Weff via HMMA: M=128(o) x N=128(i), K=256, 3-stage, 2 CTA/SM.
// ---------------------------------------------------------------------------
#define WSTG_B  32768
#define WSMEM   (1024 + 3 * WSTG_B)

__global__ __launch_bounds__(256, 2) void vera_weff_mma(const float* __restrict__ W)
{
    extern __shared__ char smem[];
    const uint32_t sb = smem_u32(smem);
    const int tid  = threadIdx.x;
    const int lane = tid & 31;
    const int wid  = tid >> 5;
    const int warp_m = wid >> 2;
    const int warp_n = wid & 3;
    const int bI = blockIdx.x;
    const int bO = blockIdx.y;

    const uint32_t FULL  = sb;
    const uint32_t EMPTY = sb + 32;
    const uint32_t STG0  = sb + 1024;

    if (tid == 0) {
        for (int s = 0; s < 3; s++) {
            MBARRIER_INIT(FULL  + 8 * s, 1);
            MBARRIER_INIT(EMPTY + 8 * s, 8);
        }
    }
    __syncthreads();

    const char* bhsrc = (const char*)g_bh  + (size_t)bO * 4 * 16384;
    const char* ahsrc = (const char*)g_ahT + (size_t)bI * 4 * 16384;

    if (tid == 0) {
#pragma unroll
        for (int s = 0; s < 3; s++) {
            const uint32_t base = STG0 + s * WSTG_B;
            MBARRIER_EXPECT_TX(FULL + 8 * s, WSTG_B);
            bulk_g2s(base,         bhsrc + (size_t)s * 16384, 16384, FULL + 8 * s);
            bulk_g2s(base + 16384, ahsrc + (size_t)s * 16384, 16384, FULL + 8 * s);
        }
    }

    const int a_row      = warp_m * 64 + (lane & 15);
    const uint32_t a_rb  = (uint32_t)a_row * 128;
    const uint32_t amsk  = (uint32_t)(lane & 7) << 4;
    const uint32_t acol0 = (uint32_t)(lane >> 4) * 16;

    const int b_rowl     = warp_n * 32 + (lane & 7) + ((lane >> 4) & 1) * 8;
    const uint32_t b_rb  = (uint32_t)b_rowl * 128;
    const uint32_t bmsk  = (uint32_t)(lane & 7) << 4;
    const uint32_t bcol0 = (uint32_t)((lane >> 3) & 1) * 16;

    float acc[4][4][4];
#pragma unroll
    for (int i = 0; i < 4; i++)
#pragma unroll
        for (int t = 0; t < 4; t++)
#pragma unroll
            for (int q = 0; q < 4; q++) acc[i][t][q] = 0.0f;

#pragma unroll 1
    for (int it = 0; it < 4; ++it) {
        const int s  = it % 3;
        const int ph = (it / 3) & 1;
        WAIT_PARITY(FULL + 8 * s, ph);
        const uint32_t XA = STG0 + s * WSTG_B;
        const uint32_t WB = XA + 16384;
#pragma unroll
        for (int ks = 0; ks < 4; ks++) {
            const uint32_t acsw = (acol0 + ks * 32) ^ amsk;
            const uint32_t bcsw = (bcol0 + ks * 32) ^ bmsk;
            uint32_t A[4][4], B[2][4];
#pragma unroll
            for (int i = 0; i < 4; i++)
                LDSM_X4(A[i], XA + a_rb + i * 2048 + acsw);
#pragma unroll
            for (int j = 0; j < 2; j++)
                LDSM_X4(B[j], WB + b_rb + j * 2048 + bcsw);
#pragma unroll
            for (int i = 0; i < 4; i++)
#pragma unroll
                for (int j = 0; j < 2; j++) {
                    MMA16816(acc[i][2 * j],     A[i], B[j][0], B[j][1]);
                    MMA16816(acc[i][2 * j + 1], A[i], B[j][2], B[j][3]);
                }
        }
        __syncwarp();
        if (lane == 0) MBARRIER_ARRIVE(EMPTY + 8 * s);
        if (tid == 0 && it + 3 < 4) {
            WAIT_PARITY(EMPTY + 8 * s, ph);
            const int nk = it + 3;
            const uint32_t base = STG0 + s * WSTG_B;
            MBARRIER_EXPECT_TX(FULL + 8 * s, WSTG_B);
            bulk_g2s(base,         bhsrc + (size_t)nk * 16384, 16384, FULL + 8 * s);
            bulk_g2s(base + 16384, ahsrc + (size_t)nk * 16384, 16384, FULL + 8 * s);
        }
    }

    const int trow0 = warp_m * 64 + (lane >> 2);
    const int col0  = warp_n * 32 + (lane & 3) * 2;

#pragma unroll
    for (int t = 0; t < 4; t++) {
        const int col = col0 + t * 8;
        const int ig  = bI * 128 + col;
        const size_t tile = ((size_t)bO * 64 + (ig >> 6)) * 16384;
        const uint32_t cu2 = (uint32_t)(ig & 63) * 2;
#pragma unroll
        for (int i = 0; i < 4; i++) {
            const int r0 = trow0 + i * 16;
            const float2 w0 = *(const float2*)&W[(size_t)(bO * 128 + r0) * IN_DIM + ig];
            const float2 w1 = *(const float2*)&W[(size_t)(bO * 128 + r0 + 8) * IN_DIM + ig];
            const uint32_t v0 = h2u(__float2half_rn(w0.x + acc[i][t][0]),
                                    __float2half_rn(w0.y + acc[i][t][1]));
            const uint32_t v1 = h2u(__float2half_rn(w1.x + acc[i][t][2]),
                                    __float2half_rn(w1.y + acc[i][t][3]));
            *(uint32_t*)((char*)g_whi + tile + sw128((uint32_t)r0 * 128 + cu2))       = v0;
            *(uint32_t*)((char*)g_whi + tile + sw128((uint32_t)(r0 + 8) * 128 + cu2)) = v1;
        }
    }
}

// ---------------------------------------------------------------------------
// Kernel 3: PERSISTENT mma.sync mainloop (R7-exact).
// ---------------------------------------------------------------------------
#define STAGES    4
#define STAGE_B   49152
#define SMEM_MAIN (1024 + STAGES * STAGE_B)

__global__ __launch_bounds__(256, 1) void vera_mma_main(
    const float* __restrict__ bias, float* __restrict__ y)
{
    extern __shared__ char smem[];
    const uint32_t sb = smem_u32(smem);
    const int tid  = threadIdx.x;
    const int lane = tid & 31;
    const int wid  = tid >> 5;
    const int bid  = blockIdx.x;

    const uint32_t FULL  = sb;
    const uint32_t EMPTY = sb + 32;
    const uint32_t STG0  = sb + 1024;

    if (tid == 0) {
        for (int s = 0; s < STAGES; s++) {
            MBARRIER_INIT(FULL  + 8 * s, 1);
            MBARRIER_INIT(EMPTY + 8 * s, 8);
        }
    }
    __syncthreads();

    const int ntile = (NTILES - 1 - bid) / NSM + 1;   // 6 or 7
    const int NITER = ntile * 64;

    // prologue fills (first tile, k = 0..3) — warp s fills stage s
    if (lane == 0 && wid < STAGES) {
        const int s = wid;
        const char* xs = (const char*)g_xhi + (size_t)((bid >> 4) * 64 + s) * 16384;
        const char* ws = (const char*)g_whi + (size_t)((bid & 15) * 2 * 64 + s) * 16384;
        const uint32_t base = STG0 + s * STAGE_B;
        MBARRIER_EXPECT_TX(FULL + 8 * s, STAGE_B);
        bulk_g2s(base,         xs, 16384, FULL + 8 * s);
        bulk_g2s(base + 16384, ws, 16384, FULL + 8 * s);
        bulk_g2s(base + 32768, ws + (size_t)64 * 16384, 16384, FULL + 8 * s);
    }

    const int warp_m = wid >> 2;
    const int warp_n = wid & 3;

    const int a_row      = warp_m * 64 + (lane & 15);
    const uint32_t a_rb  = (uint32_t)a_row * 128;
    const uint32_t amsk  = (uint32_t)(lane & 7) << 4;
    const uint32_t acol0 = (uint32_t)(lane >> 4) * 16;

    const int b_rowl     = (warp_n & 1) * 64 + (lane & 7) + ((lane >> 4) & 1) * 8;
    const uint32_t b_rb  = (uint32_t)((warp_n >> 1) * 16384 + b_rowl * 128);
    const uint32_t bmsk  = (uint32_t)(lane & 7) << 4;
    const uint32_t bcol0 = (uint32_t)((lane >> 3) & 1) * 16;

    float acc[4][8][4];
#pragma unroll
    for (int i = 0; i < 4; i++)
#pragma unroll
        for (int t = 0; t < 8; t++)
#pragma unroll
            for (int q = 0; q < 4; q++) acc[i][t][q] = 0.0f;

#pragma unroll 1
    for (int p = 0; p < NITER; ++p) {
        const int s  = p & 3;
        const int ph = (p >> 2) & 1;
        WAIT_PARITY(FULL + 8 * s, ph);
        const uint32_t XA = STG0 + s * STAGE_B;
        const uint32_t WB = XA + 16384;

#pragma unroll
        for (int ks = 0; ks < 4; ks++) {
            const uint32_t acsw = (acol0 + ks * 32) ^ amsk;
            const uint32_t bcsw = (bcol0 + ks * 32) ^ bmsk;
            uint32_t A[4][4], B[4][4];
#pragma unroll
            for (int i = 0; i < 4; i++)
                LDSM_X4(A[i], XA + a_rb + i * 2048 + acsw);
#pragma unroll
            for (int j = 0; j < 4; j++)
                LDSM_X4(B[j], WB + b_rb + j * 2048 + bcsw);
#pragma unroll
            for (int i = 0; i < 4; i++)
#pragma unroll
                for (int j = 0; j < 4; j++) {
                    MMA16816(acc[i][2 * j],     A[i], B[j][0], B[j][1]);
                    MMA16816(acc[i][2 * j + 1], A[i], B[j][2], B[j][3]);
                }
        }

        __syncwarp();
        if (lane == 0) MBARRIER_ARRIVE(EMPTY + 8 * s);

        // stage-distributed refill: warp s owns stage s
        if (wid == s && lane == 0 && p + STAGES < NITER) {
            WAIT_PARITY(EMPTY + 8 * s, ph);
            const int q    = p + STAGES;
            const int tile = bid + (q >> 6) * NSM;
            const int k    = q & 63;
            const char* xs = (const char*)g_xhi + (size_t)((tile >> 4) * 64 + k) * 16384;
            const char* ws = (const char*)g_whi + (size_t)((tile & 15) * 2 * 64 + k) * 16384;
            const uint32_t base = STG0 + s * STAGE_B;
            MBARRIER_EXPECT_TX(FULL + 8 * s, STAGE_B);
            bulk_g2s(base,         xs, 16384, FULL + 8 * s);
            bulk_g2s(base + 16384, ws, 16384, FULL + 8 * s);
            bulk_g2s(base + 32768, ws + (size_t)64 * 16384, 16384, FULL + 8 * s);
        }

        // tile epilogue
        if ((p & 63) == 63) {
            const int tile = bid + (p >> 6) * NSM;
            const int bM = tile >> 4;
            const int bN = tile & 15;
            const int trow0 = bM * 128 + warp_m * 64 + (lane >> 2);
            const int col0g = bN * 256 + warp_n * 64 + (lane & 3) * 2;
#pragma unroll
            for (int t = 0; t < 8; t++) {
                const int col = col0g + t * 8;
                const float2 bv = *(const float2*)&bias[col];
#pragma unroll
                for (int i = 0; i < 4; i++) {
                    const int r0 = trow0 + i * 16;
                    float2 o0 = make_float2(acc[i][t][0] + bv.x, acc[i][t][1] + bv.y);
                    float2 o1 = make_float2(acc[i][t][2] + bv.x, acc[i][t][3] + bv.y);
                    *(float2*)&y[(size_t)r0 * OUT_DIM + col]       = o0;
                    *(float2*)&y[(size_t)(r0 + 8) * OUT_DIM + col] = o1;
                }
            }
#pragma unroll
            for (int i = 0; i < 4; i++)
#pragma unroll
                for (int t = 0; t < 8; t++)
#pragma unroll
                    for (int q = 0; q < 4; q++) acc[i][t][q] = 0.0f;
        }
    }
}

// ---------------------------------------------------------------------------
// Launch. Inputs: x, base_weight, base_bias, vera_random_A, vera_random_B,
//                 vera_d, vera_b
//
// Graph shape (fork-join, capture-legal):
//      default:  conv ─ weff ──────────┐
//                  \                    ├─ join ─ main
//      side:        └ xprep ───────────┘
// ---------------------------------------------------------------------------
extern "C" void kernel_launch(void* const* d_in, const int* in_sizes, int n_in,
                              void* d_out, int out_size)
{
    const float* x    = (const float*)d_in[0];
    const float* W    = (const float*)d_in[1];
    const float* bias = (const float*)d_in[2];
    const float* vA   = (const float*)d_in[3];
    const float* vB   = (const float*)d_in[4];
    const float* vd   = (const float*)d_in[5];
    const float* vb   = (const float*)d_in[6];
    float* y = (float*)d_out;

    static cudaStream_t s_side = nullptr;
    static cudaEvent_t  e_fork = nullptr, e_join = nullptr;
    if (s_side == nullptr) {
        cudaStreamCreateWithFlags(&s_side, cudaStreamNonBlocking);
        cudaEventCreateWithFlags(&e_fork, cudaEventDisableTiming);
        cudaEventCreateWithFlags(&e_join, cudaEventDisableTiming);
        cudaFuncSetAttribute(vera_weff_mma,
                             cudaFuncAttributeMaxDynamicSharedMemorySize, WSMEM);
        cudaFuncSetAttribute(vera_mma_main,
                             cudaFuncAttributeMaxDynamicSharedMemorySize, SMEM_MAIN);
    }

    // fork: side stream runs x conversion concurrently with conv+weff
    cudaEventRecord(e_fork, 0);
    cudaStreamWaitEvent(s_side, e_fork, 0);
    vera_xprep<<<16384, 256, 0, s_side>>>(x);
    cudaEventRecord(e_join, s_side);

    // default stream: Bh/AhT conversion (fast transpose), then weff HMMA
    vera_conv<<<1024, 256>>>(vB, vb, vA, vd);
    dim3 gweff(IN_DIM / 128, OUT_DIM / 128);   // 32 x 32
    vera_weff_mma<<<gweff, 256, WSMEM>>>(W);

    // join, then persistent main GEMM
    cudaStreamWaitEvent(0, e_join, 0);
    vera_mma_main<<<NSM, 256, SMEM_MAIN>>>(bias, y);
}

// round 12
// speedup vs baseline: 1.0613x; 1.0037x over previous
#include <cuda_runtime.h>
#include <cuda_fp16.h>
#include <cstdint>

#define T_DIM   8192
#define IN_DIM  4096
#define OUT_DIM 4096
#define R_DIM   256
#define SCALE_F 4.0f
#define NSM     148
#define NTILES  1024   /* main: 16 (o/256) x 64 (t/128) */
#define WGROUP  80     /* phase-B CTAs doing weff; rest do xprep */

// Tiled + SW128-pre-swizzled fp16 operand buffers (16KB tiles: 128 rows x 64 cols)
__device__ __align__(128) __half g_xhi[(size_t)T_DIM  * IN_DIM];
__device__ __align__(128) __half g_whi[(size_t)OUT_DIM * IN_DIM];
__device__ __align__(128) __half g_bh [(size_t)OUT_DIM * R_DIM];
__device__ __align__(128) __half g_ahT[(size_t)IN_DIM  * R_DIM];

// monotonic grid-barrier counter (safe across graph replays: targets are
// computed as ceil(ticket/NSM)*NSM, so the counter never needs resetting)
__device__ int g_ctr;

// ---------------------------------------------------------------------------
// helpers
// ---------------------------------------------------------------------------
static __device__ __forceinline__ uint32_t sw128(uint32_t b) {
    return b ^ ((b >> 3) & 0x70);
}
static __device__ __forceinline__ uint32_t smem_u32(const void* p) {
    uint32_t a;
    asm("{ .reg .u64 t; cvta.to.shared.u64 t, %1; cvt.u32.u64 %0, t; }"
        : "=r"(a) : "l"(p));
    return a;
}
static __device__ __forceinline__ uint32_t h2u(__half a, __half b) {
    __half2 h = __halves2half2(a, b);
    return *(uint32_t*)&h;
}

#define MBARRIER_INIT(m, c) \
    asm volatile("mbarrier.init.shared.b64 [%0], %1;" :: "r"(m), "r"((uint32_t)(c)) : "memory")
#define MBARRIER_EXPECT_TX(m, b) \
    asm volatile("mbarrier.arrive.expect_tx.shared.b64 _, [%0], %1;" :: "r"(m), "r"((uint32_t)(b)) : "memory")
#define MBARRIER_ARRIVE(m) \
    asm volatile("mbarrier.arrive.shared.b64 _, [%0];" :: "r"(m) : "memory")

#define WAIT_PARITY(m, p) do {                                                    \
    uint32_t _m = (m), _p = (uint32_t)(p), _d;                                    \
    asm volatile("{\n\t.reg .pred P;\n\t"                                         \
        "mbarrier.try_wait.parity.acquire.cta.shared::cta.b64 P, [%1], %2;\n\t"   \
        "selp.b32 %0, 1, 0, P;\n\t}" : "=r"(_d) : "r"(_m), "r"(_p) : "memory");   \
    while (!_d) {                                                                 \
        asm volatile("{\n\t.reg .pred P;\n\t"                                     \
            "mbarrier.try_wait.parity.acquire.cta.shared::cta.b64 P, [%1], %2, 0x989680;\n\t" \
            "selp.b32 %0, 1, 0, P;\n\t}" : "=r"(_d) : "r"(_m), "r"(_p) : "memory"); \
    } } while (0)

static __device__ __forceinline__ void bulk_g2s(uint32_t dst, const void* src,
                                                uint32_t bytes, uint32_t mbar) {
    unsigned long long g = (unsigned long long)__cvta_generic_to_global(src);
    asm volatile("cp.async.bulk.shared::cta.global.mbarrier::complete_tx::bytes [%0], [%1], %2, [%3];"
                 :: "r"(dst), "l"(g), "r"(bytes), "r"(mbar) : "memory");
}

#define LDSM_X4(r, addr) \
    asm volatile("ldmatrix.sync.aligned.m8n8.x4.shared.b16 {%0,%1,%2,%3}, [%4];" \
                 : "=r"((r)[0]), "=r"((r)[1]), "=r"((r)[2]), "=r"((r)[3]) : "r"(addr))

#define MMA16816(c, a, b0, b1) \
    asm volatile("mma.sync.aligned.m16n8k16.row.col.f32.f16.f16.f32 " \
                 "{%0,%1,%2,%3}, {%4,%5,%6,%7}, {%8,%9}, {%0,%1,%2,%3};" \
                 : "+f"((c)[0]), "+f"((c)[1]), "+f"((c)[2]), "+f"((c)[3]) \
                 : "r"((a)[0]), "r"((a)[1]), "r"((a)[2]), "r"((a)[3]), \
                   "r"(b0), "r"(b1))

// device-wide barrier: all NSM CTAs are resident (1/SM by smem), so spinning
// is deadlock-free. Counter is monotonic; target = ceil(ticket/NSM)*NSM.
static __device__ __forceinline__ void grid_bar() {
    __threadfence();
    __syncthreads();
    __shared__ int s_tgt;
    if (threadIdx.x == 0) {
        int t = atomicAdd(&g_ctr, 1) + 1;
        s_tgt = ((t + NSM - 1) / NSM) * NSM;
    }
    __syncthreads();
    if (threadIdx.x == 0) {
        const int tgt = s_tgt;
        int v;
        do {
            asm volatile("ld.global.acquire.gpu.b32 %0, [%1];" : "=r"(v) : "l"(&g_ctr));
        } while (v < tgt);
    }
    __syncthreads();
}

// ---------------------------------------------------------------------------
// smem layout (dynamic):
//   sb+0   : 4x FULL  (phase C)        sb+32  : 4x EMPTY  (phase C)
//   sb+64  : 6x FULLB (phase B weff)   sb+112 : 6x EMPTYB (phase B weff)
//   sb+1024: stages — C: 4 x 49152 ; B: 6 x 32768 (same region, after barrier)
// ---------------------------------------------------------------------------
#define STAGES    4
#define STAGE_B   49152
#define WSTG_B    32768
#define SMEM_MAIN (1024 + STAGES * STAGE_B)   /* 197632; 6*32768=196608 fits */

__global__ __launch_bounds__(256, 1) void vera_all(
    const float* __restrict__ x,  const float* __restrict__ W,
    const float* __restrict__ vA, const float* __restrict__ vB,
    const float* __restrict__ vd, const float* __restrict__ vb,
    const float* __restrict__ bias, float* __restrict__ y)
{
    extern __shared__ char smem[];
    const uint32_t sb = smem_u32(smem);
    const int tid  = threadIdx.x;
    const int lane = tid & 31;
    const int wid  = tid >> 5;
    const int bid  = blockIdx.x;

    const uint32_t FULL   = sb;
    const uint32_t EMPTY  = sb + 32;
    const uint32_t FULLB  = sb + 64;
    const uint32_t EMPTYB = sb + 112;
    const uint32_t STG0   = sb + 1024;

    if (tid == 0) {
        for (int s = 0; s < STAGES; s++) {
            MBARRIER_INIT(FULL  + 8 * s, 1);
            MBARRIER_INIT(EMPTY + 8 * s, 8);
        }
        for (int s = 0; s < 6; s++) {
            MBARRIER_INIT(FULLB  + 8 * s, 1);
            MBARRIER_INIT(EMPTYB + 8 * s, 8);
        }
    }
    __syncthreads();

    // ======================= PHASE A: Bh + AhT conversion ===================
    for (uint32_t c = bid * 256 + tid; c < 131072; c += NSM * 256) {
        // Bh = fp16( (SCALE/64) * b[o] * vB[o][r] )
        const uint32_t o    = c >> 5;
        const uint32_t r8   = c & 31;
        const uint32_t rblk = r8 >> 3;
        const uint32_t cu   = (r8 & 7) * 8;
        const float s = __ldg(&vb[o]) * (SCALE_F / 64.0f);
        const float* src = vB + (size_t)o * R_DIM + rblk * 64 + cu;
        float4 a = *(const float4*)src;
        float4 b = *(const float4*)(src + 4);
        __half h[8] = {__float2half_rn(a.x * s), __float2half_rn(a.y * s),
                       __float2half_rn(a.z * s), __float2half_rn(a.w * s),
                       __float2half_rn(b.x * s), __float2half_rn(b.y * s),
                       __float2half_rn(b.z * s), __float2half_rn(b.w * s)};
        uint4 v = make_uint4(h2u(h[0], h[1]), h2u(h[2], h[3]),
                             h2u(h[4], h[5]), h2u(h[6], h[7]));
        const size_t tile = ((size_t)(o >> 7) * 4 + rblk) * 16384;
        *(uint4*)((char*)g_bh + tile + sw128((o & 127) * 128 + cu * 2)) = v;
    }
    for (uint32_t c = bid * 256 + tid; c < 131072; c += NSM * 256) {
        // AhT[i][r] = fp16( 64 * d[r] * vA[r][i] ) — coalesced transpose
        const uint32_t r8 = c >> 12;
        const uint32_t i  = c & 4095;
        uint32_t pk[4];
#pragma unroll
        for (int j = 0; j < 4; j++) {
            const uint32_t r0 = r8 * 8 + 2 * j;
            const float s0 = __ldg(&vd[r0])     * 64.0f;
            const float s1 = __ldg(&vd[r0 + 1]) * 64.0f;
            const float v0 = __ldg(&vA[(size_t)r0 * IN_DIM + i])       * s0;
            const float v1 = __ldg(&vA[(size_t)(r0 + 1) * IN_DIM + i]) * s1;
            pk[j] = h2u(__float2half_rn(v0), __float2half_rn(v1));
        }
        const size_t tile = ((size_t)(i >> 7) * 4 + (r8 >> 3)) * 16384;
        const uint32_t off = sw128((i & 127) * 128 + (r8 & 7) * 16);
        *(uint4*)((char*)g_ahT + tile + off) = make_uint4(pk[0], pk[1], pk[2], pk[3]);
    }

    grid_bar();

    // ============ PHASE B: weff HMMA (bid<WGROUP)  ||  xprep (rest) =========
    if (bid < WGROUP) {
        // weff: 1024 tiles (32 bO x 32 bI of 128x128), K=256 (4 chunks),
        // continuous 6-stage pipeline, stage-distributed refill (warps 0-5).
        const int ntB   = (1023 - bid) / WGROUP + 1;  // 12 or 13
        const int NITB  = ntB * 4;

        if (lane == 0 && wid < 6) {
            const int q = wid;                 // NITB >= 48 > 6, no guard
            const int tile = bid + (q >> 2) * WGROUP;
            const int k    = q & 3;
            const uint32_t base = STG0 + wid * WSTG_B;
            MBARRIER_EXPECT_TX(FULLB + 8 * wid, WSTG_B);
            bulk_g2s(base,         (char*)g_bh  + (size_t)((tile >> 5) * 4 + k) * 16384, 16384, FULLB + 8 * wid);
            bulk_g2s(base + 16384, (char*)g_ahT + (size_t)((tile & 31) * 4 + k) * 16384, 16384, FULLB + 8 * wid);
        }

        const int warp_m = wid >> 2;
        const int warp_n = wid & 3;
        const int a_row      = warp_m * 64 + (lane & 15);
        const uint32_t a_rb  = (uint32_t)a_row * 128;
        const uint32_t amsk  = (uint32_t)(lane & 7) << 4;
        const uint32_t acol0 = (uint32_t)(lane >> 4) * 16;
        const int b_rowl     = warp_n * 32 + (lane & 7) + ((lane >> 4) & 1) * 8;
        const uint32_t b_rb  = (uint32_t)b_rowl * 128;
        const uint32_t bmsk  = (uint32_t)(lane & 7) << 4;
        const uint32_t bcol0 = (uint32_t)((lane >> 3) & 1) * 16;

        float acc[4][4][4];
#pragma unroll
        for (int i = 0; i < 4; i++)
#pragma unroll
            for (int t = 0; t < 4; t++)
#pragma unroll
                for (int q = 0; q < 4; q++) acc[i][t][q] = 0.0f;

#pragma unroll 1
        for (int p = 0; p < NITB; ++p) {
            const int s  = p % 6;
            const int ph = (p / 6) & 1;
            WAIT_PARITY(FULLB + 8 * s, ph);
            const uint32_t XA = STG0 + s * WSTG_B;
            const uint32_t WB = XA + 16384;
#pragma unroll
            for (int ks = 0; ks < 4; ks++) {
                const uint32_t acsw = (acol0 + ks * 32) ^ amsk;
                const uint32_t bcsw = (bcol0 + ks * 32) ^ bmsk;
                uint32_t A[4][4], B[2][4];
#pragma unroll
                for (int i = 0; i < 4; i++)
                    LDSM_X4(A[i], XA + a_rb + i * 2048 + acsw);
#pragma unroll
                for (int j = 0; j < 2; j++)
                    LDSM_X4(B[j], WB + b_rb + j * 2048 + bcsw);
#pragma unroll
                for (int i = 0; i < 4; i++)
#pragma unroll
                    for (int j = 0; j < 2; j++) {
                        MMA16816(acc[i][2 * j],     A[i], B[j][0], B[j][1]);
                        MMA16816(acc[i][2 * j + 1], A[i], B[j][2], B[j][3]);
                    }
            }
            __syncwarp();
            if (lane == 0) MBARRIER_ARRIVE(EMPTYB + 8 * s);

            if (wid == s && lane == 0 && p + 6 < NITB) {
                WAIT_PARITY(EMPTYB + 8 * s, ph);
                const int q    = p + 6;
                const int tile = bid + (q >> 2) * WGROUP;
                const int k    = q & 3;
                const uint32_t base = STG0 + s * WSTG_B;
                MBARRIER_EXPECT_TX(FULLB + 8 * s, WSTG_B);
                bulk_g2s(base,         (char*)g_bh  + (size_t)((tile >> 5) * 4 + k) * 16384, 16384, FULLB + 8 * s);
                bulk_g2s(base + 16384, (char*)g_ahT + (size_t)((tile & 31) * 4 + k) * 16384, 16384, FULLB + 8 * s);
            }

            if ((p & 3) == 3) {   // tile epilogue: Weff = W + delta -> g_whi
                const int tile = bid + (p >> 2) * WGROUP;
                const int bO = tile >> 5;
                const int bI = tile & 31;
                const int trow0 = warp_m * 64 + (lane >> 2);
                const int col0  = warp_n * 32 + (lane & 3) * 2;
#pragma unroll
                for (int t = 0; t < 4; t++) {
                    const int col = col0 + t * 8;
                    const int ig  = bI * 128 + col;
                    const size_t gtile = ((size_t)bO * 64 + (ig >> 6)) * 16384;
                    const uint32_t cu2 = (uint32_t)(ig & 63) * 2;
#pragma unroll
                    for (int i = 0; i < 4; i++) {
                        const int r0 = trow0 + i * 16;
                        const float2 w0 = *(const float2*)&W[(size_t)(bO * 128 + r0) * IN_DIM + ig];
                        const float2 w1 = *(const float2*)&W[(size_t)(bO * 128 + r0 + 8) * IN_DIM + ig];
                        const uint32_t v0 = h2u(__float2half_rn(w0.x + acc[i][t][0]),
                                                __float2half_rn(w0.y + acc[i][t][1]));
                        const uint32_t v1 = h2u(__float2half_rn(w1.x + acc[i][t][2]),
                                                __float2half_rn(w1.y + acc[i][t][3]));
                        *(uint32_t*)((char*)g_whi + gtile + sw128((uint32_t)r0 * 128 + cu2))       = v0;
                        *(uint32_t*)((char*)g_whi + gtile + sw128((uint32_t)(r0 + 8) * 128 + cu2)) = v1;
                    }
                }
#pragma unroll
                for (int i = 0; i < 4; i++)
#pragma unroll
                    for (int t = 0; t < 4; t++)
#pragma unroll
                        for (int q = 0; q < 4; q++) acc[i][t][q] = 0.0f;
            }
        }
    } else {
        // xprep on 68 CTAs: x -> fp16 tiles (4.2M chunks of 8 elems)
        for (uint32_t c = (uint32_t)(bid - WGROUP) * 256 + tid; c < 4194304u;
             c += (uint32_t)(NSM - WGROUP) * 256) {
            const uint32_t k8   = c & 511;
            const uint32_t t    = c >> 9;
            const uint32_t kblk = k8 >> 3;
            const uint32_t cu   = (k8 & 7) * 8;
            const float* src = x + (size_t)t * IN_DIM + kblk * 64 + cu;
            float4 a = *(const float4*)src;
            float4 b = *(const float4*)(src + 4);
            __half2 p0 = __floats2half2_rn(a.x, a.y);
            __half2 p1 = __floats2half2_rn(a.z, a.w);
            __half2 p2 = __floats2half2_rn(b.x, b.y);
            __half2 p3 = __floats2half2_rn(b.z, b.w);
            uint4 v = make_uint4(*(uint32_t*)&p0, *(uint32_t*)&p1,
                                 *(uint32_t*)&p2, *(uint32_t*)&p3);
            const uint32_t off = sw128((t & 127) * 128 + cu * 2);
            *(uint4*)((char*)g_xhi + ((size_t)(t >> 7) * 64 + kblk) * 16384 + off) = v;
        }
    }

    grid_bar();

    // ======================= PHASE C: main GEMM (R7-exact) ==================
    const int ntile = (NTILES - 1 - bid) / NSM + 1;   // 6 or 7
    const int NITER = ntile * 64;

    if (lane == 0 && wid < STAGES) {
        const int s = wid;
        const char* xs = (const char*)g_xhi + (size_t)((bid >> 4) * 64 + s) * 16384;
        const char* ws = (const char*)g_whi + (size_t)((bid & 15) * 2 * 64 + s) * 16384;
        const uint32_t base = STG0 + s * STAGE_B;
        MBARRIER_EXPECT_TX(FULL + 8 * s, STAGE_B);
        bulk_g2s(base,         xs, 16384, FULL + 8 * s);
        bulk_g2s(base + 16384, ws, 16384, FULL + 8 * s);
        bulk_g2s(base + 32768, ws + (size_t)64 * 16384, 16384, FULL + 8 * s);
    }

    const int warp_m = wid >> 2;
    const int warp_n = wid & 3;
    const int a_row      = warp_m * 64 + (lane & 15);
    const uint32_t a_rb  = (uint32_t)a_row * 128;
    const uint32_t amsk  = (uint32_t)(lane & 7) << 4;
    const uint32_t acol0 = (uint32_t)(lane >> 4) * 16;
    const int b_rowl     = (warp_n & 1) * 64 + (lane & 7) + ((lane >> 4) & 1) * 8;
    const uint32_t b_rb  = (uint32_t)((warp_n >> 1) * 16384 + b_rowl * 128);
    const uint32_t bmsk  = (uint32_t)(lane & 7) << 4;
    const uint32_t bcol0 = (uint32_t)((lane >> 3) & 1) * 16;

    float acc[4][8][4];
#pragma unroll
    for (int i = 0; i < 4; i++)
#pragma unroll
        for (int t = 0; t < 8; t++)
#pragma unroll
            for (int q = 0; q < 4; q++) acc[i][t][q] = 0.0f;

#pragma unroll 1
    for (int p = 0; p < NITER; ++p) {
        const int s  = p & 3;
        const int ph = (p >> 2) & 1;
        WAIT_PARITY(FULL + 8 * s, ph);
        const uint32_t XA = STG0 + s * STAGE_B;
        const uint32_t WB = XA + 16384;

#pragma unroll
        for (int ks = 0; ks < 4; ks++) {
            const uint32_t acsw = (acol0 + ks * 32) ^ amsk;
            const uint32_t bcsw = (bcol0 + ks * 32) ^ bmsk;
            uint32_t A[4][4], B[4][4];
#pragma unroll
            for (int i = 0; i < 4; i++)
                LDSM_X4(A[i], XA + a_rb + i * 2048 + acsw);
#pragma unroll
            for (int j = 0; j < 4; j++)
                LDSM_X4(B[j], WB + b_rb + j * 2048 + bcsw);
#pragma unroll
            for (int i = 0; i < 4; i++)
#pragma unroll
                for (int j = 0; j < 4; j++) {
                    MMA16816(acc[i][2 * j],     A[i], B[j][0], B[j][1]);
                    MMA16816(acc[i][2 * j + 1], A[i], B[j][2], B[j][3]);
                }
        }

        __syncwarp();
        if (lane == 0) MBARRIER_ARRIVE(EMPTY + 8 * s);

        if (wid == s && lane == 0 && p + STAGES < NITER) {
            WAIT_PARITY(EMPTY + 8 * s, ph);
            const int q    = p + STAGES;
            const int tile = bid + (q >> 6) * NSM;
            const int k    = q & 63;
            const char* xs = (const char*)g_xhi + (size_t)((tile >> 4) * 64 + k) * 16384;
            const char* ws = (const char*)g_whi + (size_t)((tile & 15) * 2 * 64 + k) * 16384;
            const uint32_t base = STG0 + s * STAGE_B;
            MBARRIER_EXPECT_TX(FULL + 8 * s, STAGE_B);
            bulk_g2s(base,         xs, 16384, FULL + 8 * s);
            bulk_g2s(base + 16384, ws, 16384, FULL + 8 * s);
            bulk_g2s(base + 32768, ws + (size_t)64 * 16384, 16384, FULL + 8 * s);
        }

        if ((p & 63) == 63) {
            const int tile = bid + (p >> 6) * NSM;
            const int bM = tile >> 4;
            const int bN = tile & 15;
            const int trow0 = bM * 128 + warp_m * 64 + (lane >> 2);
            const int col0g = bN * 256 + warp_n * 64 + (lane & 3) * 2;
#pragma unroll
            for (int t = 0; t < 8; t++) {
                const int col = col0g + t * 8;
                const float2 bv = *(const float2*)&bias[col];
#pragma unroll
                for (int i = 0; i < 4; i++) {
                    const int r0 = trow0 + i * 16;
                    float2 o0 = make_float2(acc[i][t][0] + bv.x, acc[i][t][1] + bv.y);
                    float2 o1 = make_float2(acc[i][t][2] + bv.x, acc[i][t][3] + bv.y);
                    *(float2*)&y[(size_t)r0 * OUT_DIM + col]       = o0;
                    *(float2*)&y[(size_t)(r0 + 8) * OUT_DIM + col] = o1;
                }
            }
#pragma unroll
            for (int i = 0; i < 4; i++)
#pragma unroll
                for (int t = 0; t < 8; t++)
#pragma unroll
                    for (int q = 0; q < 4; q++) acc[i][t][q] = 0.0f;
        }
    }
}

// ---------------------------------------------------------------------------
// Launch. Inputs: x, base_weight, base_bias, vera_random_A, vera_random_B,
//                 vera_d, vera_b
// ---------------------------------------------------------------------------
extern "C" void kernel_launch(void* const* d_in, const int* in_sizes, int n_in,
                              void* d_out, int out_size)
{
    const float* x    = (const float*)d_in[0];
    const float* W    = (const float*)d_in[1];
    const float* bias = (const float*)d_in[2];
    const float* vA   = (const float*)d_in[3];
    const float* vB   = (const float*)d_in[4];
    const float* vd   = (const float*)d_in[5];
    const float* vb   = (const float*)d_in[6];
    float* y = (float*)d_out;

    cudaFuncSetAttribute(vera_all,
                         cudaFuncAttributeMaxDynamicSharedMemorySize, SMEM_MAIN);

    vera_all<<<NSM, 256, SMEM_MAIN>>>(x, W, vA, vB, vd, vb, bias, y);
}